// round 10
// baseline (speedup 1.0000x reference)
#include <cuda_runtime.h>
#include <cuda_bf16.h>
#include <math.h>
#include <stdint.h>

#define N_TOKENS 4096
#define HID      1024
#define FFN      2048
#define NEXP     8
#define NPAIR    (N_TOKENS * 2)   // 8192

// ======================= device scratch (no allocs) =======================
// fp32 path (round-1, produces the output)
__device__ __align__(256) float g_h[(size_t)NPAIR * FFN];   // 64 MB
__device__ __align__(256) float g_y[(size_t)NPAIR * HID];   // 32 MB
__device__ __align__(256) int   g_rowmap[NPAIR];
__device__ __align__(256) int   g_posof[NPAIR];
__device__ __align__(256) int   g_topk_idx[NPAIR];
__device__ __align__(256) float g_topk_prob[NPAIR];
__device__ __align__(256) int   g_counts[NEXP];
__device__ __align__(256) int   g_counts2[NEXP];
__device__ __align__(256) int   g_offsets[NEXP + 1];
// bf16 probe chain (dead scratch; results unused by output path)
__device__ __align__(256) __nv_bfloat16 g_xhi[(size_t)NPAIR * HID];
__device__ __align__(256) __nv_bfloat16 g_xlo[(size_t)NPAIR * HID];
__device__ __align__(256) __nv_bfloat16 g_w1t_hi[(size_t)NEXP * FFN * HID];
__device__ __align__(256) __nv_bfloat16 g_w1t_lo[(size_t)NEXP * FFN * HID];
__device__ __align__(256) __nv_bfloat16 g_hhi[(size_t)NPAIR * FFN];
__device__ __align__(256) __nv_bfloat16 g_hlo[(size_t)NPAIR * FFN];

// ======================= helpers =======================
__device__ __forceinline__ uint32_t smem_u32(const void* p) {
    uint32_t a;
    asm("{ .reg .u64 t; cvta.to.shared.u64 t, %1; cvt.u32.u64 %0, t; }" : "=r"(a) : "l"(p));
    return a;
}
__device__ __forceinline__ void cp_async16(uint32_t s, const void* g) {
    asm volatile("cp.async.cg.shared.global [%0], [%1], 16;" :: "r"(s), "l"(g));
}
__device__ __forceinline__ void cp_commit() { asm volatile("cp.async.commit_group;" ::: "memory"); }
__device__ __forceinline__ void cp_wait0()  { asm volatile("cp.async.wait_group 0;" ::: "memory"); }
__device__ __forceinline__ void cp_wait1()  { asm volatile("cp.async.wait_group 1;" ::: "memory"); }
__device__ __forceinline__ void ldmat_x4(uint32_t* r, uint32_t addr) {
    asm volatile("ldmatrix.sync.aligned.m8n8.x4.shared.b16 {%0,%1,%2,%3}, [%4];"
                 : "=r"(r[0]), "=r"(r[1]), "=r"(r[2]), "=r"(r[3]) : "r"(addr));
}
__device__ __forceinline__ void mma16816(float* c, const uint32_t* a, uint32_t b0, uint32_t b1) {
    asm volatile("mma.sync.aligned.m16n8k16.row.col.f32.bf16.bf16.f32 "
                 "{%0,%1,%2,%3},{%4,%5,%6,%7},{%8,%9},{%0,%1,%2,%3};"
                 : "+f"(c[0]), "+f"(c[1]), "+f"(c[2]), "+f"(c[3])
                 : "r"(a[0]), "r"(a[1]), "r"(a[2]), "r"(a[3]), "r"(b0), "r"(b1));
}
__device__ __forceinline__ float gelu_exact(float v) {
    return 0.5f * v * (1.0f + erff(v * 0.70710678118654752f));
}

// ======================= routing (round-1, known good) =======================
__global__ void init_kernel() {
    int i = threadIdx.x;
    if (i < NEXP) { g_counts[i] = 0; g_counts2[i] = 0; }
}

__global__ void router_kernel(const float* __restrict__ x, const float* __restrict__ rw) {
    int t = blockIdx.x, tid = threadIdx.x, w = tid >> 5, lane = tid & 31;
    const float* xr = x + (size_t)t * HID;
    float s = 0.f;
#pragma unroll 8
    for (int i = lane; i < HID; i += 32) s += xr[i] * rw[i * NEXP + w];
#pragma unroll
    for (int o = 16; o; o >>= 1) s += __shfl_xor_sync(0xffffffffu, s, o);
    __shared__ float logits[NEXP];
    if (lane == 0) logits[w] = s;
    __syncthreads();
    if (tid == 0) {
        float mx = logits[0];
#pragma unroll
        for (int e = 1; e < NEXP; e++) mx = fmaxf(mx, logits[e]);
        float p[NEXP], den = 0.f;
#pragma unroll
        for (int e = 0; e < NEXP; e++) { p[e] = expf(logits[e] - mx); den += p[e]; }
        int i0 = 0;
#pragma unroll
        for (int e = 1; e < NEXP; e++) if (p[e] > p[i0]) i0 = e;
        int i1 = (i0 == 0) ? 1 : 0;
#pragma unroll
        for (int e = 0; e < NEXP; e++) if (e != i0 && p[e] > p[i1]) i1 = e;
        float inv = 1.f / den;
        g_topk_idx[2 * t] = i0;      g_topk_idx[2 * t + 1] = i1;
        g_topk_prob[2 * t] = p[i0] * inv; g_topk_prob[2 * t + 1] = p[i1] * inv;
        atomicAdd(&g_counts[i0], 1); atomicAdd(&g_counts[i1], 1);
    }
}

__global__ void offsets_kernel() {
    int o = 0;
#pragma unroll
    for (int e = 0; e < NEXP; e++) { g_offsets[e] = o; o += g_counts[e]; }
    g_offsets[NEXP] = o;
}

__global__ void scatter_kernel() {
    int p = blockIdx.x * blockDim.x + threadIdx.x;
    if (p >= NPAIR) return;
    int e = g_topk_idx[p];
    int pos = g_offsets[e] + atomicAdd(&g_counts2[e], 1);
    g_rowmap[pos] = p >> 1;
    g_posof[p] = pos;
}

// ============ probe chain: gather/transpose + HMMA GEMM1 (dead output) ============
__global__ void transpose_split_kernel(const float* __restrict__ in,
                                       __nv_bfloat16* __restrict__ ohi,
                                       __nv_bfloat16* __restrict__ olo,
                                       int R, int C) {
    __shared__ float t[32][33];
    int c0 = blockIdx.x * 32, r0 = blockIdx.y * 32;
    int tx = threadIdx.x, ty = threadIdx.y;
#pragma unroll
    for (int i = 0; i < 4; i++)
        t[ty + i * 8][tx] = in[(size_t)(r0 + ty + i * 8) * C + c0 + tx];
    __syncthreads();
#pragma unroll
    for (int i = 0; i < 4; i++) {
        float v = t[tx][ty + i * 8];
        __nv_bfloat16 h = __float2bfloat16(v);
        __nv_bfloat16 l = __float2bfloat16(v - __bfloat162float(h));
        size_t o = (size_t)(c0 + ty + i * 8) * R + r0 + tx;
        ohi[o] = h;
        olo[o] = l;
    }
}

__global__ void gather_split_kernel(const float* __restrict__ x) {
    int pos = blockIdx.x, tx = threadIdx.x;
    int token = g_rowmap[pos];
    float4 v = ((const float4*)(x + (size_t)token * HID))[tx];
    __nv_bfloat16 h[4], l[4];
    float vv[4] = {v.x, v.y, v.z, v.w};
#pragma unroll
    for (int j = 0; j < 4; j++) {
        h[j] = __float2bfloat16(vv[j]);
        l[j] = __float2bfloat16(vv[j] - __bfloat162float(h[j]));
    }
    size_t o = (size_t)pos * HID + tx * 4;
    *(uint64_t*)(g_xhi + o) = *(const uint64_t*)h;
    *(uint64_t*)(g_xlo + o) = *(const uint64_t*)l;
}

#define ROWB      48
#define TILE_B    (128 * ROWB)
#define STAGE_B   (4 * TILE_B)       // 24576
#define SMEM_DYN  (2 * STAGE_B)      // 49152

template <int KTOT>
__global__ __launch_bounds__(256) void moe_gemm_hmma_probe(
    const __nv_bfloat16* __restrict__ Ahi, const __nv_bfloat16* __restrict__ Alo, int lda,
    const __nv_bfloat16* __restrict__ Bhi, const __nv_bfloat16* __restrict__ Blo,
    size_t estride, int ldbn)
{
    const int e = blockIdx.z;
    const int start = g_offsets[e], end = g_offsets[e + 1];
    const int m0 = start + blockIdx.y * 128;
    if (m0 >= end) return;
    const int n0 = blockIdx.x * 128;

    extern __shared__ char dsm[];
    const uint32_t sb = smem_u32(dsm);

    const int tid  = threadIdx.x;
    const int lane = tid & 31;
    const int wid  = tid >> 5;
    const int wm0  = (wid & 1) * 64;
    const int wn0  = (wid >> 1) * 32;

    const int r0i = tid >> 1, c2 = tid & 1;
    int mA = m0 + r0i; if (mA >= end) mA = end - 1;
    const __nv_bfloat16* gAh = Ahi + (size_t)mA * lda + c2 * 8;
    const __nv_bfloat16* gAl = Alo + (size_t)mA * lda + c2 * 8;
    const __nv_bfloat16* gBh = Bhi + e * estride + (size_t)(n0 + r0i) * ldbn + c2 * 8;
    const __nv_bfloat16* gBl = Blo + e * estride + (size_t)(n0 + r0i) * ldbn + c2 * 8;
    const uint32_t so = r0i * ROWB + c2 * 16;

    const uint32_t aoff = (wm0 + (lane & 15)) * ROWB + (lane >> 4) * 16;
    const uint32_t boff = (wn0 + ((lane >> 4) & 1) * 8 + (lane & 7)) * ROWB + ((lane >> 3) & 1) * 16;

    float acc[4][4][4];
#pragma unroll
    for (int i = 0; i < 4; i++)
#pragma unroll
        for (int j = 0; j < 4; j++)
#pragma unroll
            for (int q = 0; q < 4; q++) acc[i][j][q] = 0.f;

    constexpr int NST = KTOT / 16;

    auto issue = [&](int s) {
        const int kt = s * 16;
        const uint32_t base = sb + (s & 1) * STAGE_B;
        cp_async16(base + so,              gAh + kt);
        cp_async16(base + TILE_B + so,     gAl + kt);
        cp_async16(base + 2 * TILE_B + so, gBh + kt);
        cp_async16(base + 3 * TILE_B + so, gBl + kt);
    };

    issue(0);
    cp_commit();

    for (int s = 0; s < NST; s++) {
        if (s + 1 < NST) { issue(s + 1); cp_commit(); cp_wait1(); }
        else             { cp_wait0(); }
        __syncthreads();

        const uint32_t base = sb + (s & 1) * STAGE_B;
        uint32_t ah[4][4], al[4][4];
#pragma unroll
        for (int mt = 0; mt < 4; mt++) {
            ldmat_x4(ah[mt], base + aoff + mt * (16 * ROWB));
            ldmat_x4(al[mt], base + TILE_B + aoff + mt * (16 * ROWB));
        }
        uint32_t bh[2][4], bl[2][4];
#pragma unroll
        for (int nb = 0; nb < 2; nb++) {
            ldmat_x4(bh[nb], base + 2 * TILE_B + boff + nb * (16 * ROWB));
            ldmat_x4(bl[nb], base + 3 * TILE_B + boff + nb * (16 * ROWB));
        }
#pragma unroll
        for (int mt = 0; mt < 4; mt++)
#pragma unroll
            for (int nb = 0; nb < 2; nb++)
#pragma unroll
                for (int j = 0; j < 2; j++) {
                    float* c = acc[mt][nb * 2 + j];
                    mma16816(c, ah[mt], bh[nb][j * 2], bh[nb][j * 2 + 1]);
                    mma16816(c, ah[mt], bl[nb][j * 2], bl[nb][j * 2 + 1]);
                    mma16816(c, al[mt], bh[nb][j * 2], bh[nb][j * 2 + 1]);
                }
        __syncthreads();
    }

    const int rbase = m0 + wm0 + (lane >> 2);
    const int cbase = n0 + wn0 + (lane & 3) * 2;
#pragma unroll
    for (int mt = 0; mt < 4; mt++) {
#pragma unroll
        for (int nt = 0; nt < 4; nt++) {
            const float* c = acc[mt][nt];
            int col = cbase + nt * 8;
            int rlo = rbase + mt * 16;
            int rhi = rlo + 8;
            if (rlo < end) {
                float v0 = gelu_exact(c[0]), v1 = gelu_exact(c[1]);
                __nv_bfloat16 h0 = __float2bfloat16(v0), h1 = __float2bfloat16(v1);
                __nv_bfloat162 hh; hh.x = h0; hh.y = h1;
                __nv_bfloat162 ll;
                ll.x = __float2bfloat16(v0 - __bfloat162float(h0));
                ll.y = __float2bfloat16(v1 - __bfloat162float(h1));
                *(__nv_bfloat162*)&g_hhi[(size_t)rlo * FFN + col] = hh;
                *(__nv_bfloat162*)&g_hlo[(size_t)rlo * FFN + col] = ll;
            }
            if (rhi < end) {
                float v0 = gelu_exact(c[2]), v1 = gelu_exact(c[3]);
                __nv_bfloat16 h0 = __float2bfloat16(v0), h1 = __float2bfloat16(v1);
                __nv_bfloat162 hh; hh.x = h0; hh.y = h1;
                __nv_bfloat162 ll;
                ll.x = __float2bfloat16(v0 - __bfloat162float(h0));
                ll.y = __float2bfloat16(v1 - __bfloat162float(h1));
                *(__nv_bfloat162*)&g_hhi[(size_t)rhi * FFN + col] = hh;
                *(__nv_bfloat162*)&g_hlo[(size_t)rhi * FFN + col] = ll;
            }
        }
    }
}

// ======================= SIMT GEMMs (round-1, produce output) =======================
__global__ __launch_bounds__(256) void simt_gemm1_kernel(const float* __restrict__ x,
                                                         const float* __restrict__ w1) {
    const int e     = blockIdx.z;
    const int start = g_offsets[e];
    const int end   = g_offsets[e + 1];
    const int m0    = start + blockIdx.y * 64;
    if (m0 >= end) return;
    const int n0 = blockIdx.x * 64;

    __shared__ __align__(16) float As[16][68];
    __shared__ __align__(16) float Bs[16][64];

    const int tid = threadIdx.x;
    const int tx  = tid & 15;
    const int ty  = tid >> 4;

    const int arow = tid >> 2;
    const int ak   = (tid & 3) * 4;
    const int r    = m0 + arow;
    const int token = g_rowmap[(r < end) ? r : start];
    const float* aptr = x + (size_t)token * HID + ak;

    const int bk = tid >> 4;
    const int bn = (tid & 15) * 4;
    const float* bptr = w1 + (size_t)e * FFN + n0 + bn;

    float acc[4][4];
#pragma unroll
    for (int i = 0; i < 4; i++)
#pragma unroll
        for (int j = 0; j < 4; j++) acc[i][j] = 0.f;

    for (int kt = 0; kt < HID; kt += 16) {
        float4 av = *(const float4*)(aptr + kt);
        float4 bv = *(const float4*)(bptr + (size_t)(kt + bk) * (NEXP * FFN));
        As[ak + 0][arow] = av.x;
        As[ak + 1][arow] = av.y;
        As[ak + 2][arow] = av.z;
        As[ak + 3][arow] = av.w;
        *(float4*)&Bs[bk][bn] = bv;
        __syncthreads();
#pragma unroll
        for (int kk = 0; kk < 16; kk++) {
            float4 a = *(const float4*)&As[kk][ty * 4];
            float4 b = *(const float4*)&Bs[kk][tx * 4];
            acc[0][0] += a.x * b.x; acc[0][1] += a.x * b.y; acc[0][2] += a.x * b.z; acc[0][3] += a.x * b.w;
            acc[1][0] += a.y * b.x; acc[1][1] += a.y * b.y; acc[1][2] += a.y * b.z; acc[1][3] += a.y * b.w;
            acc[2][0] += a.z * b.x; acc[2][1] += a.z * b.y; acc[2][2] += a.z * b.z; acc[2][3] += a.z * b.w;
            acc[3][0] += a.w * b.x; acc[3][1] += a.w * b.y; acc[3][2] += a.w * b.z; acc[3][3] += a.w * b.w;
        }
        __syncthreads();
    }

#pragma unroll
    for (int i = 0; i < 4; i++) {
        int rr = m0 + ty * 4 + i;
        if (rr < end) {
            float4 o;
            o.x = gelu_exact(acc[i][0]);
            o.y = gelu_exact(acc[i][1]);
            o.z = gelu_exact(acc[i][2]);
            o.w = gelu_exact(acc[i][3]);
            *(float4*)&g_h[(size_t)rr * FFN + n0 + tx * 4] = o;
        }
    }
}

__global__ __launch_bounds__(256) void simt_gemm2_kernel(const float* __restrict__ w2) {
    const int e     = blockIdx.z;
    const int start = g_offsets[e];
    const int end   = g_offsets[e + 1];
    const int m0    = start + blockIdx.y * 64;
    if (m0 >= end) return;
    const int n0 = blockIdx.x * 64;

    __shared__ __align__(16) float As[16][68];
    __shared__ __align__(16) float Bs[16][64];

    const int tid = threadIdx.x;
    const int tx  = tid & 15;
    const int ty  = tid >> 4;

    const int arow = tid >> 2;
    const int ak   = (tid & 3) * 4;
    const int r    = m0 + arow;
    const int rsafe = (r < end) ? r : start;
    const float* aptr = g_h + (size_t)rsafe * FFN + ak;

    const int bk = tid >> 4;
    const int bn = (tid & 15) * 4;
    const float* bptr = w2 + (size_t)e * FFN * HID + n0 + bn;

    float acc[4][4];
#pragma unroll
    for (int i = 0; i < 4; i++)
#pragma unroll
        for (int j = 0; j < 4; j++) acc[i][j] = 0.f;

    for (int kt = 0; kt < FFN; kt += 16) {
        float4 av = *(const float4*)(aptr + kt);
        float4 bv = *(const float4*)(bptr + (size_t)(kt + bk) * HID);
        As[ak + 0][arow] = av.x;
        As[ak + 1][arow] = av.y;
        As[ak + 2][arow] = av.z;
        As[ak + 3][arow] = av.w;
        *(float4*)&Bs[bk][bn] = bv;
        __syncthreads();
#pragma unroll
        for (int kk = 0; kk < 16; kk++) {
            float4 a = *(const float4*)&As[kk][ty * 4];
            float4 b = *(const float4*)&Bs[kk][tx * 4];
            acc[0][0] += a.x * b.x; acc[0][1] += a.x * b.y; acc[0][2] += a.x * b.z; acc[0][3] += a.x * b.w;
            acc[1][0] += a.y * b.x; acc[1][1] += a.y * b.y; acc[1][2] += a.y * b.z; acc[1][3] += a.y * b.w;
            acc[2][0] += a.z * b.x; acc[2][1] += a.z * b.y; acc[2][2] += a.z * b.z; acc[2][3] += a.z * b.w;
            acc[3][0] += a.w * b.x; acc[3][1] += a.w * b.y; acc[3][2] += a.w * b.z; acc[3][3] += a.w * b.w;
        }
        __syncthreads();
    }

#pragma unroll
    for (int i = 0; i < 4; i++) {
        int rr = m0 + ty * 4 + i;
        if (rr < end) {
            float4 o;
            o.x = acc[i][0]; o.y = acc[i][1]; o.z = acc[i][2]; o.w = acc[i][3];
            *(float4*)&g_y[(size_t)rr * HID + n0 + tx * 4] = o;
        }
    }
}

// ======================= combine =======================
__global__ void combine_kernel(float* __restrict__ out) {
    const int HC = HID / 4;
    int idx = blockIdx.x * blockDim.x + threadIdx.x;
    if (idx >= N_TOKENS * HC) return;
    int t = idx / HC, c = idx % HC;
    float p0 = g_topk_prob[2 * t], p1 = g_topk_prob[2 * t + 1];
    int pos0 = g_posof[2 * t], pos1 = g_posof[2 * t + 1];
    float4 y0 = *(const float4*)&g_y[(size_t)pos0 * HID + c * 4];
    float4 y1 = *(const float4*)&g_y[(size_t)pos1 * HID + c * 4];
    float4 o;
    o.x = p0 * y0.x + p1 * y1.x; o.y = p0 * y0.y + p1 * y1.y;
    o.z = p0 * y0.z + p1 * y1.z; o.w = p0 * y0.w + p1 * y1.w;
    *(float4*)&out[(size_t)t * HID + c * 4] = o;
}

// ======================= launch =======================
extern "C" void kernel_launch(void* const* d_in, const int* in_sizes, int n_in,
                              void* d_out, int out_size) {
    const float* x  = (const float*)d_in[0];
    const float* rw = (const float*)d_in[1];
    const float* w1 = (const float*)d_in[2];
    const float* w2 = (const float*)d_in[3];
    float* out = (float*)d_out;

    // Belt-and-braces: opt in the probe kernel to its 48KB dynamic smem even
    // though 49152B should be within the default limit. Harmless if redundant.
    cudaFuncSetAttribute(moe_gemm_hmma_probe<1024>,
                         cudaFuncAttributeMaxDynamicSharedMemorySize, SMEM_DYN);

    // routing (known good)
    init_kernel<<<1, 32>>>();
    router_kernel<<<N_TOKENS, 256>>>(x, rw);
    offsets_kernel<<<1, 1>>>();
    scatter_kernel<<<NPAIR / 256, 256>>>();

    // ---- probe chain (dead output; measures whether HMMA machinery executes)
    gather_split_kernel<<<NPAIR, 256>>>(x);
    transpose_split_kernel<<<dim3((NEXP * FFN) / 32, HID / 32), dim3(32, 8)>>>(
        w1, g_w1t_hi, g_w1t_lo, HID, NEXP * FFN);
    moe_gemm_hmma_probe<1024><<<dim3(FFN / 128, NPAIR / 128, NEXP), 256, SMEM_DYN>>>(
        g_xhi, g_xlo, HID, g_w1t_hi, g_w1t_lo, (size_t)FFN * HID, HID);

    // ---- output path (round-1 SIMT, known good)
    simt_gemm1_kernel<<<dim3(FFN / 64, NPAIR / 64, NEXP), 256>>>(x, w1);
    simt_gemm2_kernel<<<dim3(HID / 64, NPAIR / 64, NEXP), 256>>>(w2);
    combine_kernel<<<(N_TOKENS * (HID / 4) + 255) / 256, 256>>>(out);
}

// round 11
// speedup vs baseline: 2.9058x; 2.9058x over previous
#include <cuda_runtime.h>
#include <math.h>
#include <stdint.h>

#define N_TOKENS 4096
#define HID      1024
#define FFN      2048
#define NEXP     8
#define NPAIR    (N_TOKENS * 2)   // 8192

// ======================= device scratch (no allocs) =======================
__device__ __align__(256) float g_h[(size_t)NPAIR * FFN];   // 64 MB
__device__ __align__(256) float g_y[(size_t)NPAIR * HID];   // 32 MB
__device__ __align__(256) int   g_rowmap[NPAIR];
__device__ __align__(256) int   g_posof[NPAIR];
__device__ __align__(256) int   g_topk_idx[NPAIR];
__device__ __align__(256) float g_topk_prob[NPAIR];
__device__ __align__(256) int   g_counts[NEXP];
__device__ __align__(256) int   g_counts2[NEXP];
__device__ __align__(256) int   g_offsets[NEXP + 1];

// ======================= helpers =======================
// Packed dual-fp32 FMA (Blackwell FFMA2): c(2xf32) += a(2xf32) * b(2xf32)
#define FMA_F32X2(c, a, b) \
    asm("fma.rn.f32x2 %0, %1, %2, %0;" : "+l"(c) : "l"(a), "l"(b))

__device__ __forceinline__ uint64_t dup2(float v) {
    uint32_t b = __float_as_uint(v);
    return ((uint64_t)b << 32) | b;
}
__device__ __forceinline__ float lo32f(uint64_t v) { return __uint_as_float((uint32_t)v); }
__device__ __forceinline__ float hi32f(uint64_t v) { return __uint_as_float((uint32_t)(v >> 32)); }

__device__ __forceinline__ float gelu_exact(float v) {
    return 0.5f * v * (1.0f + erff(v * 0.70710678118654752f));
}

// ======================= routing (known good) =======================
__global__ void init_kernel() {
    int i = threadIdx.x;
    if (i < NEXP) { g_counts[i] = 0; g_counts2[i] = 0; }
}

__global__ void router_kernel(const float* __restrict__ x, const float* __restrict__ rw) {
    int t = blockIdx.x, tid = threadIdx.x, w = tid >> 5, lane = tid & 31;
    const float* xr = x + (size_t)t * HID;
    float s = 0.f;
#pragma unroll 8
    for (int i = lane; i < HID; i += 32) s += xr[i] * rw[i * NEXP + w];
#pragma unroll
    for (int o = 16; o; o >>= 1) s += __shfl_xor_sync(0xffffffffu, s, o);
    __shared__ float logits[NEXP];
    if (lane == 0) logits[w] = s;
    __syncthreads();
    if (tid == 0) {
        float mx = logits[0];
#pragma unroll
        for (int e = 1; e < NEXP; e++) mx = fmaxf(mx, logits[e]);
        float p[NEXP], den = 0.f;
#pragma unroll
        for (int e = 0; e < NEXP; e++) { p[e] = expf(logits[e] - mx); den += p[e]; }
        int i0 = 0;
#pragma unroll
        for (int e = 1; e < NEXP; e++) if (p[e] > p[i0]) i0 = e;
        int i1 = (i0 == 0) ? 1 : 0;
#pragma unroll
        for (int e = 0; e < NEXP; e++) if (e != i0 && p[e] > p[i1]) i1 = e;
        float inv = 1.f / den;
        g_topk_idx[2 * t] = i0;      g_topk_idx[2 * t + 1] = i1;
        g_topk_prob[2 * t] = p[i0] * inv; g_topk_prob[2 * t + 1] = p[i1] * inv;
        atomicAdd(&g_counts[i0], 1); atomicAdd(&g_counts[i1], 1);
    }
}

__global__ void offsets_kernel() {
    int o = 0;
#pragma unroll
    for (int e = 0; e < NEXP; e++) { g_offsets[e] = o; o += g_counts[e]; }
    g_offsets[NEXP] = o;
}

__global__ void scatter_kernel() {
    int p = blockIdx.x * blockDim.x + threadIdx.x;
    if (p >= NPAIR) return;
    int e = g_topk_idx[p];
    int pos = g_offsets[e] + atomicAdd(&g_counts2[e], 1);
    g_rowmap[pos] = p >> 1;
    g_posof[p] = pos;
}

// ======================= grouped FFMA2 GEMM =======================
// Tile M=64 N=64 BK=32, 256 threads, 4x4 micro-tile as 8 packed f32x2 accs.
// As2: pre-duplicated (a,a) uint64, row stride 65 (STS.64 2-way max).
// Bs:  plain floats, row stride 68 (STS.128/LDS.128 conflict-free).
// MODE 0: A = x gathered via g_rowmap, epilogue gelu -> g_h
// MODE 1: A = g_h, epilogue identity -> g_y
template <int KTOT, int MODE>
__global__ __launch_bounds__(256) void moe_gemm_f32x2(
    const float* __restrict__ x,   // MODE 0 only
    const float* __restrict__ B,   // w1 or w2
    size_t estride, int ldb)
{
    const int e     = blockIdx.z;
    const int start = g_offsets[e];
    const int end   = g_offsets[e + 1];
    const int m0    = start + blockIdx.y * 64;
    if (m0 >= end) return;
    const int n0 = blockIdx.x * 64;

    __shared__ uint64_t As2[32][65];
    __shared__ __align__(16) float Bs[32][68];

    const int tid = threadIdx.x;
    const int tx  = tid & 15;      // n group
    const int ty  = tid >> 4;      // m group

    // A loader: thread owns row arow, k chunk ak..ak+7
    const int arow = tid >> 2;
    const int ak   = (tid & 3) * 8;
    int r = m0 + arow; if (r >= end) r = end - 1;
    const float* aptr;
    if (MODE == 0) aptr = x + (size_t)g_rowmap[r] * HID + ak;
    else           aptr = g_h + (size_t)r * FFN + ak;

    // B loader: thread owns k row bk, n chunk bn..bn+7 (B is [k][n], n contiguous)
    const int bk = tid >> 3;
    const int bn = (tid & 7) * 8;
    const float* bptr = B + e * estride + (size_t)bk * ldb + n0 + bn;

    uint64_t acc[4][2];
#pragma unroll
    for (int i = 0; i < 4; i++) { acc[i][0] = 0; acc[i][1] = 0; }

    for (int kt = 0; kt < KTOT; kt += 32) {
        float4 a0 = *(const float4*)(aptr + kt);
        float4 a1 = *(const float4*)(aptr + kt + 4);
        float4 b0 = *(const float4*)(bptr + (size_t)kt * ldb);
        float4 b1 = *(const float4*)(bptr + (size_t)kt * ldb + 4);

        As2[ak + 0][arow] = dup2(a0.x);
        As2[ak + 1][arow] = dup2(a0.y);
        As2[ak + 2][arow] = dup2(a0.z);
        As2[ak + 3][arow] = dup2(a0.w);
        As2[ak + 4][arow] = dup2(a1.x);
        As2[ak + 5][arow] = dup2(a1.y);
        As2[ak + 6][arow] = dup2(a1.z);
        As2[ak + 7][arow] = dup2(a1.w);
        *(float4*)&Bs[bk][bn]     = b0;
        *(float4*)&Bs[bk][bn + 4] = b1;
        __syncthreads();

#pragma unroll
        for (int kk = 0; kk < 32; kk++) {
            uint64_t ad0 = As2[kk][ty * 4 + 0];
            uint64_t ad1 = As2[kk][ty * 4 + 1];
            uint64_t ad2 = As2[kk][ty * 4 + 2];
            uint64_t ad3 = As2[kk][ty * 4 + 3];
            ulonglong2 bp = *(const ulonglong2*)&Bs[kk][tx * 4];   // (b0,b1),(b2,b3)
            FMA_F32X2(acc[0][0], ad0, bp.x); FMA_F32X2(acc[0][1], ad0, bp.y);
            FMA_F32X2(acc[1][0], ad1, bp.x); FMA_F32X2(acc[1][1], ad1, bp.y);
            FMA_F32X2(acc[2][0], ad2, bp.x); FMA_F32X2(acc[2][1], ad2, bp.y);
            FMA_F32X2(acc[3][0], ad3, bp.x); FMA_F32X2(acc[3][1], ad3, bp.y);
        }
        __syncthreads();
    }

    // epilogue: thread covers rows m0+ty*4..+3, cols n0+tx*4..+3
    const int cbase = n0 + tx * 4;
#pragma unroll
    for (int i = 0; i < 4; i++) {
        int rr = m0 + ty * 4 + i;
        if (rr < end) {
            float4 o;
            o.x = lo32f(acc[i][0]); o.y = hi32f(acc[i][0]);
            o.z = lo32f(acc[i][1]); o.w = hi32f(acc[i][1]);
            if (MODE == 0) {
                o.x = gelu_exact(o.x); o.y = gelu_exact(o.y);
                o.z = gelu_exact(o.z); o.w = gelu_exact(o.w);
                *(float4*)&g_h[(size_t)rr * FFN + cbase] = o;
            } else {
                *(float4*)&g_y[(size_t)rr * HID + cbase] = o;
            }
        }
    }
}

// ======================= combine =======================
__global__ void combine_kernel(float* __restrict__ out) {
    const int HC = HID / 4;
    int idx = blockIdx.x * blockDim.x + threadIdx.x;
    if (idx >= N_TOKENS * HC) return;
    int t = idx / HC, c = idx % HC;
    float p0 = g_topk_prob[2 * t], p1 = g_topk_prob[2 * t + 1];
    int pos0 = g_posof[2 * t], pos1 = g_posof[2 * t + 1];
    float4 y0 = *(const float4*)&g_y[(size_t)pos0 * HID + c * 4];
    float4 y1 = *(const float4*)&g_y[(size_t)pos1 * HID + c * 4];
    float4 o;
    o.x = p0 * y0.x + p1 * y1.x; o.y = p0 * y0.y + p1 * y1.y;
    o.z = p0 * y0.z + p1 * y1.z; o.w = p0 * y0.w + p1 * y1.w;
    *(float4*)&out[(size_t)t * HID + c * 4] = o;
}

// ======================= launch =======================
extern "C" void kernel_launch(void* const* d_in, const int* in_sizes, int n_in,
                              void* d_out, int out_size) {
    const float* x  = (const float*)d_in[0];
    const float* rw = (const float*)d_in[1];
    const float* w1 = (const float*)d_in[2];
    const float* w2 = (const float*)d_in[3];
    float* out = (float*)d_out;

    init_kernel<<<1, 32>>>();
    router_kernel<<<N_TOKENS, 256>>>(x, rw);
    offsets_kernel<<<1, 1>>>();
    scatter_kernel<<<NPAIR / 256, 256>>>();

    // GEMM1: h = gelu(x_gathered @ w1_e)   [K=HID]  B rows stride NEXP*FFN
    moe_gemm_f32x2<1024, 0><<<dim3(FFN / 64, NPAIR / 64, NEXP), 256>>>(
        x, w1, (size_t)FFN, NEXP * FFN);

    // GEMM2: y = h @ w2_e                  [K=FFN]  B rows stride HID
    moe_gemm_f32x2<2048, 1><<<dim3(HID / 64, NPAIR / 64, NEXP), 256>>>(
        nullptr, w2, (size_t)FFN * HID, HID);

    combine_kernel<<<(N_TOKENS * (HID / 4) + 255) / 256, 256>>>(out);
}